// round 15
// baseline (speedup 1.0000x reference)
#include <cuda_runtime.h>
#include <math.h>
#include <stdint.h>

#define B 64
#define T 4096
#define D 512
#define SPLITS 32
#define CHUNK (T / SPLITS)          // 128 rows of T per CTA
#define THREADS 256                 // 8 warps per CTA
#define ROWS_PER_WARP (CHUNK / 8)   // 16

// Scratch (no allocation allowed anywhere)
__device__ float g_k[B * D];
__device__ float g_pm[B * SPLITS];
__device__ float g_ps[B * SPLITS];
__device__ float g_pacc[B * SPLITS * D];        // 4 MB

// ---- packed f32x2 helpers (sm_103a; ptxas never auto-fuses these) ----------
__device__ __forceinline__ uint64_t f2pack(float lo, float hi) {
    uint64_t r; asm("mov.b64 %0, {%1, %2};" : "=l"(r) : "f"(lo), "f"(hi));
    return r;
}
__device__ __forceinline__ void f2unpack(uint64_t v, float& lo, float& hi) {
    asm("mov.b64 {%0, %1}, %2;" : "=f"(lo), "=f"(hi) : "l"(v));
}
__device__ __forceinline__ uint64_t fma2(uint64_t a, uint64_t b, uint64_t c) {
    uint64_t d;
    asm("fma.rn.f32x2 %0, %1, %2, %3;" : "=l"(d) : "l"(a), "l"(b), "l"(c));
    return d;
}
__device__ __forceinline__ uint64_t mul2(uint64_t a, uint64_t b) {
    uint64_t d;
    asm("mul.rn.f32x2 %0, %1, %2;" : "=l"(d) : "l"(a), "l"(b));
    return d;
}

// ---------------------------------------------------------------------------
// Kernel 1: k = query @ W^T + bias.  Warp computes a 4b x 4d tile.
// (unchanged from R14: 7.5us)
// ---------------------------------------------------------------------------
__global__ __launch_bounds__(128)
void key_kernel(const float* __restrict__ query,
                const float* __restrict__ W,
                const float* __restrict__ bias) {
    const int wid  = threadIdx.x >> 5;
    const int lane = threadIdx.x & 31;
    const int warp = blockIdx.x * 4 + wid;      // 0..2047
    const int d0   = (warp & 127) * 4;          // 128 d-tiles
    const int b0   = (warp >> 7) * 4;           // 16  b-tiles

    const float4* Wp = (const float4*)W;        // row = 128 float4
    const float4* Qp = (const float4*)query;

    float4 w[4][4];
    #pragma unroll
    for (int i = 0; i < 4; i++)
        #pragma unroll
        for (int j = 0; j < 4; j++)
            w[i][j] = Wp[(size_t)(d0 + i) * 128 + lane + 32 * j];

    #pragma unroll
    for (int bi = 0; bi < 4; bi++) {
        float4 q4[4];
        #pragma unroll
        for (int j = 0; j < 4; j++)
            q4[j] = Qp[(size_t)(b0 + bi) * 128 + lane + 32 * j];

        float p[4];
        #pragma unroll
        for (int i = 0; i < 4; i++) {
            float s0 = 0.f, s1 = 0.f, s2 = 0.f, s3 = 0.f;
            #pragma unroll
            for (int j = 0; j < 4; j++) {
                s0 = fmaf(w[i][j].x, q4[j].x, s0);
                s1 = fmaf(w[i][j].y, q4[j].y, s1);
                s2 = fmaf(w[i][j].z, q4[j].z, s2);
                s3 = fmaf(w[i][j].w, q4[j].w, s3);
            }
            p[i] = (s0 + s1) + (s2 + s3);
        }
        #pragma unroll
        for (int off = 16; off; off >>= 1)
            #pragma unroll
            for (int i = 0; i < 4; i++)
                p[i] += __shfl_xor_sync(0xffffffffu, p[i], off);
        if (lane == 0) {
            #pragma unroll
            for (int i = 0; i < 4; i++)
                g_k[(size_t)(b0 + bi) * D + d0 + i] = p[i] + bias[d0 + i];
        }
    }
}

// ---------------------------------------------------------------------------
// Kernel 2: fused scores + masked online softmax + weighted accumulation.
// R12/R14 structure, but ALL vector math in packed f32x2 (halved FMA issue):
// row data + k pairs arrive pre-packed via 128-bit loads into ulonglong2,
// accumulator lives packed (bit-identical layout to old float4 path).
// ---------------------------------------------------------------------------
__global__ __launch_bounds__(THREADS, 3)
void attn_partial_kernel(const float* __restrict__ attend_to,
                         const int* __restrict__ mask) {   // bool -> int32
    __shared__ float  k_sh[D];                 // 2 KB
    __shared__ float4 sm_acc[8][D / 4];        // 16 KB (end-phase)
    __shared__ float  sm_m[8], sm_s[8];

    const int b    = blockIdx.y;
    const int sp   = blockIdx.x;
    const int tid  = threadIdx.x;
    const int wid  = tid >> 5;
    const int lane = tid & 31;
    const int trow0 = sp * CHUNK + wid * ROWS_PER_WARP;

    for (int i = tid; i < D; i += THREADS) k_sh[i] = g_k[(size_t)b * D + i];

    // Warp's ROWS_PER_WARP(=16) mask bits gathered into one ballot word.
    int mv = 0;
    if (lane < ROWS_PER_WARP)
        mv = __ldg(&mask[(size_t)(trow0 + lane) * B + b]);
    const unsigned mbits = __ballot_sync(0xffffffffu, mv != 0);

    // Row = 128 ulonglong2 (each .x/.y is a packed f32x2 pair)
    const ulonglong2* rp =
        (const ulonglong2*)(attend_to + ((size_t)b * T + trow0) * D);

    uint64_t c[8];
    {   ulonglong2 v0 = rp[lane],      v1 = rp[lane + 32],
                   v2 = rp[lane + 64], v3 = rp[lane + 96];
        c[0] = v0.x; c[1] = v0.y; c[2] = v1.x; c[3] = v1.y;
        c[4] = v2.x; c[5] = v2.y; c[6] = v3.x; c[7] = v3.y; }

    __syncthreads();                           // k_sh ready
    const ulonglong2* ks2 = (const ulonglong2*)k_sh;

    float m = -INFINITY, s = 0.f;
    uint64_t a[8] = {0, 0, 0, 0, 0, 0, 0, 0}; // bits of {0.f,0.f}

    #pragma unroll 2
    for (int i = 0; i < ROWS_PER_WARP; i++) {
        // Prefetch next row into registers
        uint64_t n[8];
        if (i + 1 < ROWS_PER_WARP) {
            const ulonglong2* nr = rp + (size_t)(i + 1) * (D / 4);
            ulonglong2 v0 = nr[lane],      v1 = nr[lane + 32],
                       v2 = nr[lane + 64], v3 = nr[lane + 96];
            n[0] = v0.x; n[1] = v0.y; n[2] = v1.x; n[3] = v1.y;
            n[4] = v2.x; n[5] = v2.y; n[6] = v3.x; n[7] = v3.y;
        }

        // Row dot with k: 8 packed FMAs in 2 chains, then horizontal add
        {
            ulonglong2 kv0 = ks2[lane],      kv1 = ks2[lane + 32],
                       kv2 = ks2[lane + 64], kv3 = ks2[lane + 96];
            uint64_t dA = mul2(c[0], kv0.x);
            uint64_t dB = mul2(c[1], kv0.y);
            dA = fma2(c[2], kv1.x, dA);
            dB = fma2(c[3], kv1.y, dB);
            dA = fma2(c[4], kv2.x, dA);
            dB = fma2(c[5], kv2.y, dB);
            dA = fma2(c[6], kv3.x, dA);
            dB = fma2(c[7], kv3.y, dB);
            float la, ha, lb, hb;
            f2unpack(dA, la, ha);
            f2unpack(dB, lb, hb);
            float sc = (la + ha) + (lb + hb);
            #pragma unroll
            for (int off = 16; off; off >>= 1)
                sc += __shfl_xor_sync(0xffffffffu, sc, off);
            if ((mbits >> i) & 1u) sc = -INFINITY;

            // Online softmax update (branches warp-uniform)
            if (sc > m) {
                float corr = __expf(m - sc);   // m=-inf -> corr=0 first row
                s = s * corr + 1.0f;
                uint64_t c2 = f2pack(corr, corr);
                #pragma unroll
                for (int j = 0; j < 8; j++) a[j] = fma2(a[j], c2, c[j]);
                m = sc;
            } else if (sc != -INFINITY) {
                float p = __expf(sc - m);
                s += p;
                uint64_t p2 = f2pack(p, p);
                #pragma unroll
                for (int j = 0; j < 8; j++) a[j] = fma2(c[j], p2, a[j]);
            }
        }
        #pragma unroll
        for (int j = 0; j < 8; j++) c[j] = n[j];
    }

    // ---- End-phase: combine 8 warps -> one CTA partial ----
    // Packed pairs have the same byte layout as the float4 path.
    {
        ulonglong2* sa2 = (ulonglong2*)sm_acc[wid];
        sa2[lane]      = make_ulonglong2(a[0], a[1]);
        sa2[lane + 32] = make_ulonglong2(a[2], a[3]);
        sa2[lane + 64] = make_ulonglong2(a[4], a[5]);
        sa2[lane + 96] = make_ulonglong2(a[6], a[7]);
    }
    if (lane == 0) { sm_m[wid] = m; sm_s[wid] = s; }
    __syncthreads();

    float M = -INFINITY;
    #pragma unroll
    for (int w = 0; w < 8; w++) M = fmaxf(M, sm_m[w]);
    float wts[8];
    float stot = 0.f;
    #pragma unroll
    for (int w = 0; w < 8; w++) {
        float mw = sm_m[w];
        float wt = (mw == -INFINITY) ? 0.f : __expf(mw - M);
        wts[w] = wt;
        stot += wt * sm_s[w];
    }

    const float* sa = (const float*)sm_acc;   // [8][512]
    float v0 = 0.f, v1 = 0.f;
    #pragma unroll
    for (int w = 0; w < 8; w++) {
        v0 += wts[w] * sa[w * D + tid];
        v1 += wts[w] * sa[w * D + tid + THREADS];
    }

    const int pi = b * SPLITS + sp;
    g_pacc[(size_t)pi * D + tid]           = v0;
    g_pacc[(size_t)pi * D + tid + THREADS] = v1;
    if (tid == 0) { g_pm[pi] = M; g_ps[pi] = stot; }
}

// ---------------------------------------------------------------------------
// Kernel 3: combine SPLITS partials per batch row. grid = (B, 2).
// ---------------------------------------------------------------------------
__global__ __launch_bounds__(256)
void combine_kernel(float* __restrict__ out) {
    const int b = blockIdx.x;
    const int c = blockIdx.y * 256 + threadIdx.x;

    float M = -INFINITY;
    #pragma unroll
    for (int i = 0; i < SPLITS; i++) M = fmaxf(M, g_pm[b * SPLITS + i]);

    float stot = 0.f, sum = 0.f;
    #pragma unroll
    for (int i = 0; i < SPLITS; i++) {
        float mi = g_pm[b * SPLITS + i];
        float w = (mi == -INFINITY) ? 0.f : __expf(mi - M);
        stot += g_ps[b * SPLITS + i] * w;
        sum  += g_pacc[(size_t)(b * SPLITS + i) * D + c] * w;
    }
    out[(size_t)b * D + c] = sum / stot;
}

// ---------------------------------------------------------------------------
// Inputs (metadata order): query [B,D] f32, attend_to [B,T,D] f32,
// mask [T,B] bool->int32, W [D,D] f32, b [D] f32. Output: [B,1,D] f32.
// ---------------------------------------------------------------------------
extern "C" void kernel_launch(void* const* d_in, const int* in_sizes, int n_in,
                              void* d_out, int out_size) {
    const float* query  = (const float*)d_in[0];
    const float* attend = (const float*)d_in[1];
    const int*   mask   = (const int*)d_in[2];
    const float* W      = (const float*)d_in[3];
    const float* bias   = (const float*)d_in[4];
    float* out = (float*)d_out;

    key_kernel<<<512, 128>>>(query, W, bias);
    attn_partial_kernel<<<dim3(SPLITS, B), THREADS>>>(attend, mask);
    combine_kernel<<<dim3(B, 2), 256>>>(out);
}